// round 1
// baseline (speedup 1.0000x reference)
#include <cuda_runtime.h>
#include <math.h>

#define Bdim 32
#define Tdim 1024
#define DIdim 512
#define Hdim 512
#define NG (4*Hdim)

// Scratch (device globals are the sanctioned scratch mechanism)
__device__ float g_G[Tdim*Bdim*NG];     // 268MB: [t][b][gate*512+j] = x@W + bias
__device__ float g_h[2][Bdim*Hdim];     // double-buffered hidden state
__device__ unsigned int g_bar;          // grid barrier counter

// ---------------------------------------------------------------------------
// init: load h0, reset barrier (must run every replay for determinism)
// ---------------------------------------------------------------------------
__global__ void init_kernel(const float* __restrict__ init_states) {
    int i = blockIdx.x * blockDim.x + threadIdx.x;
    if (i < Bdim*Hdim) {
        g_h[0][i] = init_states[i];          // init_states[0] = h0
    }
    if (blockIdx.x == 0 && threadIdx.x == 0) g_bar = 0u;
}

// ---------------------------------------------------------------------------
// Precompute G = X @ W_all + bias   (M=32768, N=2048, K=512) fp32 SGEMM
// Output row m = t*32 + b  (so recurrence reads G[t][b][*] contiguously)
// ---------------------------------------------------------------------------
__global__ __launch_bounds__(256) void xw_kernel(
    const float* __restrict__ X,
    const float* __restrict__ Wi, const float* __restrict__ Wf,
    const float* __restrict__ Wc, const float* __restrict__ Wo,
    const float* __restrict__ bi, const float* __restrict__ bf,
    const float* __restrict__ bc, const float* __restrict__ bo)
{
    __shared__ float As[16][64];
    __shared__ float Bs[16][64];

    const int tid = threadIdx.x;
    const int mbase = blockIdx.x * 64;
    const int nbase = blockIdx.y * 64;
    const int gate = nbase >> 9;          // 64-wide N tiles never straddle gates
    const int col0 = nbase & 511;

    const float* W    = (gate==0) ? Wi : (gate==1) ? Wf : (gate==2) ? Wc : Wo;
    const float* bias = (gate==0) ? bi : (gate==1) ? bf : (gate==2) ? bc : bo;

    // A tile loader: 64 rows x 16 k, float4 along k
    const int a_m = tid >> 2;             // 0..63
    const int a_k = (tid & 3) * 4;        // 0,4,8,12
    const int m   = mbase + a_m;          // m = t*32 + b
    const int bb  = m & 31;
    const int tt  = m >> 5;
    const float* xrow = X + ((size_t)bb * Tdim + tt) * DIdim;

    // B tile loader: 16 k x 64 n, float4 along n
    const int b_k = tid >> 4;             // 0..15
    const int b_n = (tid & 15) * 4;       // 0..60
    const float* wbase = W + (size_t)b_k * Hdim + col0 + b_n;

    const int tx = tid & 15, ty = tid >> 4;

    float acc[4][4];
    #pragma unroll
    for (int i = 0; i < 4; i++)
        #pragma unroll
        for (int j = 0; j < 4; j++) acc[i][j] = 0.f;

    for (int k0 = 0; k0 < DIdim; k0 += 16) {
        float4 av = *(const float4*)(xrow + k0 + a_k);
        As[a_k+0][a_m] = av.x; As[a_k+1][a_m] = av.y;
        As[a_k+2][a_m] = av.z; As[a_k+3][a_m] = av.w;
        float4 bv = *(const float4*)(wbase + (size_t)k0 * Hdim);
        *(float4*)&Bs[b_k][b_n] = bv;
        __syncthreads();
        #pragma unroll
        for (int k = 0; k < 16; k++) {
            float4 a4 = *(const float4*)&As[k][ty*4];
            float4 b4 = *(const float4*)&Bs[k][tx*4];
            acc[0][0] += a4.x*b4.x; acc[0][1] += a4.x*b4.y; acc[0][2] += a4.x*b4.z; acc[0][3] += a4.x*b4.w;
            acc[1][0] += a4.y*b4.x; acc[1][1] += a4.y*b4.y; acc[1][2] += a4.y*b4.z; acc[1][3] += a4.y*b4.w;
            acc[2][0] += a4.z*b4.x; acc[2][1] += a4.z*b4.y; acc[2][2] += a4.z*b4.z; acc[2][3] += a4.z*b4.w;
            acc[3][0] += a4.w*b4.x; acc[3][1] += a4.w*b4.y; acc[3][2] += a4.w*b4.z; acc[3][3] += a4.w*b4.w;
        }
        __syncthreads();
    }

    float4 bias4 = *(const float4*)(bias + col0 + tx*4);
    #pragma unroll
    for (int i = 0; i < 4; i++) {
        int mm = mbase + ty*4 + i;
        float4 o;
        o.x = acc[i][0] + bias4.x;
        o.y = acc[i][1] + bias4.y;
        o.z = acc[i][2] + bias4.z;
        o.w = acc[i][3] + bias4.w;
        *(float4*)(g_G + (size_t)mm * NG + nbase + tx*4) = o;
    }
}

// ---------------------------------------------------------------------------
// Persistent recurrence. 128 CTAs x 256 threads (1/SM, co-resident).
// CTA tile: 8 batches x 16 hidden columns. Thread: (kc 0..15, bpair 0..3, jg 0..3)
// -> 2 batches x 4 cols x 4 gates over a 32-wide K chunk (32 fp32 accumulators).
// c state lives in registers of the owner thread. h via global double buffer.
// ---------------------------------------------------------------------------
__global__ __launch_bounds__(256,1) void lstm_kernel(
    const float* __restrict__ Ui, const float* __restrict__ Uf,
    const float* __restrict__ Uc, const float* __restrict__ Uo,
    const float* __restrict__ init_states,
    float* __restrict__ out)
{
    // union'd smem: h stage (8 x 516 = 4128 floats) vs partials (256 x 33 = 8448)
    __shared__ __align__(16) float sm[256*33];

    const int tid  = threadIdx.x;
    const int jblk = (blockIdx.x & 31) * 16;  // 32 j-blocks of 16
    const int b0   = (blockIdx.x >> 5) * 8;   // 4  b-blocks of 8

    const int kc = tid >> 4;        // 0..15 (K chunk of 32)
    const int p  = (tid >> 2) & 3;  // batch pair
    const int jg = tid & 3;         // 4-col group
    const int j0 = jblk + jg*4;
    const int kstart = kc * 32;

    const float4* pUi = (const float4*)Ui + (size_t)kstart*(Hdim/4) + (j0 >> 2);
    const float4* pUf = (const float4*)Uf + (size_t)kstart*(Hdim/4) + (j0 >> 2);
    const float4* pUc = (const float4*)Uc + (size_t)kstart*(Hdim/4) + (j0 >> 2);
    const float4* pUo = (const float4*)Uo + (size_t)kstart*(Hdim/4) + (j0 >> 2);

    // elementwise-owner mapping (tid < 128: one (b,j) cell each)
    const int e_bl = tid >> 4;
    const int e_jl = tid & 15;
    const int e_b  = b0 + e_bl;
    const int e_j  = jblk + e_jl;
    const int e_p2 = e_bl >> 1;
    const int e_b2 = e_bl & 1;
    const int e_jg = e_jl >> 2;
    const int e_jj = e_jl & 3;
    const int e_idx = e_b * Hdim + e_j;

    float cstate = 0.f;
    if (tid < 128) cstate = init_states[Bdim*Hdim + e_idx];   // c0

    for (int t = 0; t < Tdim; t++) {
        // ---- stage h_prev (L1-bypassing: written by other SMs last step) ----
        const float4* hsrc = (const float4*)(g_h[t & 1] + b0 * Hdim);
        #pragma unroll
        for (int i = 0; i < 4; i++) {
            int idx = tid + i*256;        // 0..1023 float4s (8 rows x 128)
            float4 v = __ldcg(hsrc + idx);
            int bl = idx >> 7;
            int k4 = idx & 127;
            *(float4*)&sm[bl*516 + k4*4] = v;
        }
        __syncthreads();

        // ---- partial GEMM: 2 batches x 16 (gate,col) over 32 k ----
        float acc0[16], acc1[16];
        #pragma unroll
        for (int v = 0; v < 16; v++) { acc0[v] = 0.f; acc1[v] = 0.f; }

        const float* h0p = &sm[(2*p  )*516 + kstart];
        const float* h1p = &sm[(2*p+1)*516 + kstart];
        #pragma unroll 4
        for (int k = 0; k < 32; k++) {
            float4 vi = pUi[(size_t)k*128];
            float4 vf = pUf[(size_t)k*128];
            float4 vc = pUc[(size_t)k*128];
            float4 vo = pUo[(size_t)k*128];
            float h0 = h0p[k];
            float h1 = h1p[k];
            acc0[0]  += h0*vi.x; acc0[1]  += h0*vi.y; acc0[2]  += h0*vi.z; acc0[3]  += h0*vi.w;
            acc0[4]  += h0*vf.x; acc0[5]  += h0*vf.y; acc0[6]  += h0*vf.z; acc0[7]  += h0*vf.w;
            acc0[8]  += h0*vc.x; acc0[9]  += h0*vc.y; acc0[10] += h0*vc.z; acc0[11] += h0*vc.w;
            acc0[12] += h0*vo.x; acc0[13] += h0*vo.y; acc0[14] += h0*vo.z; acc0[15] += h0*vo.w;
            acc1[0]  += h1*vi.x; acc1[1]  += h1*vi.y; acc1[2]  += h1*vi.z; acc1[3]  += h1*vi.w;
            acc1[4]  += h1*vf.x; acc1[5]  += h1*vf.y; acc1[6]  += h1*vf.z; acc1[7]  += h1*vf.w;
            acc1[8]  += h1*vc.x; acc1[9]  += h1*vc.y; acc1[10] += h1*vc.z; acc1[11] += h1*vc.w;
            acc1[12] += h1*vo.x; acc1[13] += h1*vo.y; acc1[14] += h1*vo.z; acc1[15] += h1*vo.w;
        }
        __syncthreads();   // sm reused: h stage -> partial buffer

        {
            float* row = &sm[tid*33];
            #pragma unroll
            for (int v = 0; v < 16; v++) row[v]    = acc0[v];
            #pragma unroll
            for (int v = 0; v < 16; v++) row[16+v] = acc1[v];
        }
        __syncthreads();

        // ---- reduce over kc + elementwise LSTM cell ----
        if (tid < 128) {
            float z0 = 0.f, z1 = 0.f, z2 = 0.f, z3 = 0.f;
            #pragma unroll
            for (int q = 0; q < 16; q++) {
                const float* r = &sm[(q*16 + e_p2*4 + e_jg)*33 + e_b2*16];
                z0 += r[0*4 + e_jj];
                z1 += r[1*4 + e_jj];
                z2 += r[2*4 + e_jj];
                z3 += r[3*4 + e_jj];
            }
            const float* gr = g_G + ((size_t)t * Bdim + e_b) * NG + e_j;
            z0 += gr[0];     // i
            z1 += gr[512];   // f
            z2 += gr[1024];  // g
            z3 += gr[1536];  // o
            float iv = 1.f / (1.f + __expf(-z0));
            float fv = 1.f / (1.f + __expf(-z1));
            float gv = tanhf(z2);
            float ov = 1.f / (1.f + __expf(-z3));
            cstate = fv * cstate + iv * gv;
            float hn = ov * tanhf(cstate);
            g_h[(t+1) & 1][e_idx] = hn;
            out[((size_t)e_b * Tdim + t) * Hdim + e_j] = hn;
        }

        // ---- grid barrier (release: fence + relaxed add; acquire poll) ----
        __threadfence();
        __syncthreads();
        if (tid == 0) {
            atomicAdd(&g_bar, 1u);
            unsigned target = (unsigned)gridDim.x * (unsigned)(t + 1);
            unsigned v;
            do {
                asm volatile("ld.acquire.gpu.global.u32 %0, [%1];" : "=r"(v) : "l"(&g_bar));
            } while (v < target);
        }
        __syncthreads();
    }
}

// ---------------------------------------------------------------------------
extern "C" void kernel_launch(void* const* d_in, const int* in_sizes, int n_in,
                              void* d_out, int out_size) {
    const float* X           = (const float*)d_in[0];
    const float* init_states = (const float*)d_in[1];
    const float* Wi = (const float*)d_in[2];
    const float* Ui = (const float*)d_in[3];
    const float* bi = (const float*)d_in[4];
    const float* Wf = (const float*)d_in[5];
    const float* Uf = (const float*)d_in[6];
    const float* bf = (const float*)d_in[7];
    const float* Wc = (const float*)d_in[8];
    const float* Uc = (const float*)d_in[9];
    const float* bc = (const float*)d_in[10];
    const float* Wo = (const float*)d_in[11];
    const float* Uo = (const float*)d_in[12];
    const float* bo = (const float*)d_in[13];
    float* out = (float*)d_out;

    init_kernel<<<(Bdim*Hdim + 255)/256, 256>>>(init_states);

    dim3 gemm_grid((Bdim*Tdim)/64, NG/64);   // (512, 32)
    xw_kernel<<<gemm_grid, 256>>>(X, Wi, Wf, Wc, Wo, bi, bf, bc, bo);

    lstm_kernel<<<128, 256>>>(Ui, Uf, Uc, Uo, init_states, out);
}

// round 2
// speedup vs baseline: 1.1578x; 1.1578x over previous
#include <cuda_runtime.h>
#include <math.h>

#define Bdim 32
#define Tdim 1024
#define DIdim 512
#define Hdim 512
#define NG (4*Hdim)

// Scratch (device globals are the sanctioned scratch mechanism)
__device__ float g_G[Tdim*Bdim*NG];          // 268MB: [t][b][gate*512+j] = x@W + bias
__device__ unsigned g_A[Tdim*Bdim*DIdim];    // 64MB: tf32(X) gathered, row m=t*32+b
__device__ unsigned g_Wt[DIdim*NG];          // 16MB: tf32(W) fused [k][gate*512+c]
__device__ float g_bias[NG];                 // fused bias
__device__ float g_h[2][Bdim*Hdim];          // double-buffered hidden state
__device__ unsigned int g_bar;               // grid barrier counter

__device__ __forceinline__ unsigned f2tf32(float f) {
    unsigned r;
    asm("cvt.rna.tf32.f32 %0, %1;" : "=r"(r) : "f"(f));
    return r;
}

// ---------------------------------------------------------------------------
// init: load h0, reset barrier, build fused bias
// ---------------------------------------------------------------------------
__global__ void init_kernel(const float* __restrict__ init_states,
                            const float* __restrict__ bi, const float* __restrict__ bf,
                            const float* __restrict__ bc, const float* __restrict__ bo)
{
    int i = blockIdx.x * blockDim.x + threadIdx.x;
    if (i < Bdim*Hdim) {
        g_h[0][i] = init_states[i];          // init_states[0] = h0
    }
    if (i < NG) {
        int gate = i >> 9, c = i & 511;
        const float* b = (gate==0) ? bi : (gate==1) ? bf : (gate==2) ? bc : bo;
        g_bias[i] = b[c];
    }
    if (i == 0) g_bar = 0u;
}

// ---------------------------------------------------------------------------
// prep_x: gather X[b][t][k] -> A[m=t*32+b][k] as tf32 (rna)
// ---------------------------------------------------------------------------
__global__ __launch_bounds__(256) void prep_x_kernel(const float* __restrict__ X) {
    int idx = blockIdx.x * blockDim.x + threadIdx.x;   // float4 index
    // total f4 = 32768*512/4 = 4194304
    int m  = idx >> 7;          // 128 f4 per row
    int k4 = idx & 127;
    int b = m & 31, t = m >> 5;
    float4 v = *(const float4*)(X + ((size_t)b * Tdim + t) * DIdim + k4*4);
    uint4 o;
    o.x = f2tf32(v.x); o.y = f2tf32(v.y); o.z = f2tf32(v.z); o.w = f2tf32(v.w);
    *(uint4*)(g_A + (size_t)m * DIdim + k4*4) = o;
}

// ---------------------------------------------------------------------------
// prep_w: fuse Wi|Wf|Wc|Wo -> Wt[k][gate*512+c] as tf32
// ---------------------------------------------------------------------------
__global__ __launch_bounds__(256) void prep_w_kernel(
    const float* __restrict__ Wi, const float* __restrict__ Wf,
    const float* __restrict__ Wc, const float* __restrict__ Wo)
{
    int idx = blockIdx.x * blockDim.x + threadIdx.x;   // f4 index, total 262144
    int gate = idx >> 16;
    int rem  = idx & 65535;
    int k  = rem >> 7;
    int c4 = rem & 127;
    const float* W = (gate==0) ? Wi : (gate==1) ? Wf : (gate==2) ? Wc : Wo;
    float4 v = *(const float4*)(W + (size_t)k * Hdim + c4*4);
    uint4 o;
    o.x = f2tf32(v.x); o.y = f2tf32(v.y); o.z = f2tf32(v.z); o.w = f2tf32(v.w);
    *(uint4*)(g_Wt + (size_t)k * NG + gate*512 + c4*4) = o;
}

// ---------------------------------------------------------------------------
// xw GEMM via mma.sync m16n8k8 tf32:
// C[32768,2048] = A[32768,512] @ Wt[512,2048] + bias  -> g_G (fp32)
// CTA tile 128x64, 8 warps (4 m x 2 n), warp tile 32x32, K-chunk 32
// ---------------------------------------------------------------------------
__device__ __forceinline__ void mma_tf32(float* d, const unsigned* a, const unsigned* b) {
    asm volatile(
        "mma.sync.aligned.m16n8k8.row.col.f32.tf32.tf32.f32 "
        "{%0,%1,%2,%3}, {%4,%5,%6,%7}, {%8,%9}, {%0,%1,%2,%3};"
        : "+f"(d[0]), "+f"(d[1]), "+f"(d[2]), "+f"(d[3])
        : "r"(a[0]), "r"(a[1]), "r"(a[2]), "r"(a[3]), "r"(b[0]), "r"(b[1]));
}

#define AS_PAD 36
#define BS_PAD 68

__global__ __launch_bounds__(256) void xw_mma_kernel() {
    __shared__ unsigned As[128 * AS_PAD];
    __shared__ unsigned Bs[32 * BS_PAD];

    const int tid = threadIdx.x;
    const int wid = tid >> 5;
    const int lane = tid & 31;
    const int gid = lane >> 2;      // group id 0..7
    const int tig = lane & 3;       // thread in group 0..3

    const int warp_m = (wid & 3) * 32;
    const int warp_n = (wid >> 2) * 32;

    const int mbase = blockIdx.x * 128;
    const int nbase = blockIdx.y * 64;

    float acc[2][4][4];
    #pragma unroll
    for (int mt = 0; mt < 2; mt++)
        #pragma unroll
        for (int nt = 0; nt < 4; nt++)
            #pragma unroll
            for (int r = 0; r < 4; r++) acc[mt][nt][r] = 0.f;

    // staging indices
    // A: 128 rows x 32 k = 1024 uint4 -> 4 per thread
    const int a_row = tid >> 1;           // used with +128 rows pattern below
    // B: 32 rows x 64 n = 512 uint4 -> 2 per thread

    for (int k0 = 0; k0 < DIdim; k0 += 32) {
        // stage A chunk
        #pragma unroll
        for (int r = 0; r < 4; r++) {
            int i = tid + r * 256;        // uint4 index 0..1023
            int row = i >> 3;
            int k4 = (i & 7) * 4;
            uint4 v = *(const uint4*)(g_A + (size_t)(mbase + row) * DIdim + k0 + k4);
            *(uint4*)&As[row * AS_PAD + k4] = v;
        }
        // stage B chunk
        #pragma unroll
        for (int r = 0; r < 2; r++) {
            int i = tid + r * 256;        // uint4 index 0..511
            int krow = i >> 4;
            int n4 = (i & 15) * 4;
            uint4 v = *(const uint4*)(g_Wt + (size_t)(k0 + krow) * NG + nbase + n4);
            *(uint4*)&Bs[krow * BS_PAD + n4] = v;
        }
        __syncthreads();

        #pragma unroll
        for (int ks = 0; ks < 4; ks++) {
            const int k8 = ks * 8;
            unsigned af[2][4];
            #pragma unroll
            for (int mt = 0; mt < 2; mt++) {
                int row = warp_m + mt*16 + gid;
                af[mt][0] = As[(row    ) * AS_PAD + k8 + tig    ];
                af[mt][1] = As[(row + 8) * AS_PAD + k8 + tig    ];
                af[mt][2] = As[(row    ) * AS_PAD + k8 + tig + 4];
                af[mt][3] = As[(row + 8) * AS_PAD + k8 + tig + 4];
            }
            unsigned bf2[4][2];
            #pragma unroll
            for (int nt = 0; nt < 4; nt++) {
                int col = warp_n + nt*8 + gid;
                bf2[nt][0] = Bs[(k8 + tig    ) * BS_PAD + col];
                bf2[nt][1] = Bs[(k8 + tig + 4) * BS_PAD + col];
            }
            #pragma unroll
            for (int mt = 0; mt < 2; mt++)
                #pragma unroll
                for (int nt = 0; nt < 4; nt++)
                    mma_tf32(acc[mt][nt], af[mt], bf2[nt]);
        }
        __syncthreads();
    }

    // epilogue: + bias, store fp32 to g_G
    #pragma unroll
    for (int mt = 0; mt < 2; mt++) {
        #pragma unroll
        for (int nt = 0; nt < 4; nt++) {
            int col = nbase + warp_n + nt*8 + 2*tig;
            float b0 = g_bias[col];
            float b1 = g_bias[col + 1];
            int row0 = mbase + warp_m + mt*16 + gid;
            float2 o0 = make_float2(acc[mt][nt][0] + b0, acc[mt][nt][1] + b1);
            float2 o1 = make_float2(acc[mt][nt][2] + b0, acc[mt][nt][3] + b1);
            *(float2*)(g_G + (size_t)row0 * NG + col)       = o0;
            *(float2*)(g_G + (size_t)(row0 + 8) * NG + col) = o1;
        }
    }
    (void)a_row;
}

// ---------------------------------------------------------------------------
// Persistent recurrence (UNCHANGED from round 1 — known correct).
// 128 CTAs x 256 threads (1/SM). CTA tile: 8 batches x 16 hidden columns.
// ---------------------------------------------------------------------------
__global__ __launch_bounds__(256,1) void lstm_kernel(
    const float* __restrict__ Ui, const float* __restrict__ Uf,
    const float* __restrict__ Uc, const float* __restrict__ Uo,
    const float* __restrict__ init_states,
    float* __restrict__ out)
{
    __shared__ __align__(16) float sm[256*33];

    const int tid  = threadIdx.x;
    const int jblk = (blockIdx.x & 31) * 16;  // 32 j-blocks of 16
    const int b0   = (blockIdx.x >> 5) * 8;   // 4  b-blocks of 8

    const int kc = tid >> 4;        // 0..15 (K chunk of 32)
    const int p  = (tid >> 2) & 3;  // batch pair
    const int jg = tid & 3;         // 4-col group
    const int j0 = jblk + jg*4;
    const int kstart = kc * 32;

    const float4* pUi = (const float4*)Ui + (size_t)kstart*(Hdim/4) + (j0 >> 2);
    const float4* pUf = (const float4*)Uf + (size_t)kstart*(Hdim/4) + (j0 >> 2);
    const float4* pUc = (const float4*)Uc + (size_t)kstart*(Hdim/4) + (j0 >> 2);
    const float4* pUo = (const float4*)Uo + (size_t)kstart*(Hdim/4) + (j0 >> 2);

    const int e_bl = tid >> 4;
    const int e_jl = tid & 15;
    const int e_b  = b0 + e_bl;
    const int e_j  = jblk + e_jl;
    const int e_p2 = e_bl >> 1;
    const int e_b2 = e_bl & 1;
    const int e_jg = e_jl >> 2;
    const int e_jj = e_jl & 3;
    const int e_idx = e_b * Hdim + e_j;

    float cstate = 0.f;
    if (tid < 128) cstate = init_states[Bdim*Hdim + e_idx];   // c0

    for (int t = 0; t < Tdim; t++) {
        const float4* hsrc = (const float4*)(g_h[t & 1] + b0 * Hdim);
        #pragma unroll
        for (int i = 0; i < 4; i++) {
            int idx = tid + i*256;
            float4 v = __ldcg(hsrc + idx);
            int bl = idx >> 7;
            int k4 = idx & 127;
            *(float4*)&sm[bl*516 + k4*4] = v;
        }
        __syncthreads();

        float acc0[16], acc1[16];
        #pragma unroll
        for (int v = 0; v < 16; v++) { acc0[v] = 0.f; acc1[v] = 0.f; }

        const float* h0p = &sm[(2*p  )*516 + kstart];
        const float* h1p = &sm[(2*p+1)*516 + kstart];
        #pragma unroll 4
        for (int k = 0; k < 32; k++) {
            float4 vi = pUi[(size_t)k*128];
            float4 vf = pUf[(size_t)k*128];
            float4 vc = pUc[(size_t)k*128];
            float4 vo = pUo[(size_t)k*128];
            float h0 = h0p[k];
            float h1 = h1p[k];
            acc0[0]  += h0*vi.x; acc0[1]  += h0*vi.y; acc0[2]  += h0*vi.z; acc0[3]  += h0*vi.w;
            acc0[4]  += h0*vf.x; acc0[5]  += h0*vf.y; acc0[6]  += h0*vf.z; acc0[7]  += h0*vf.w;
            acc0[8]  += h0*vc.x; acc0[9]  += h0*vc.y; acc0[10] += h0*vc.z; acc0[11] += h0*vc.w;
            acc0[12] += h0*vo.x; acc0[13] += h0*vo.y; acc0[14] += h0*vo.z; acc0[15] += h0*vo.w;
            acc1[0]  += h1*vi.x; acc1[1]  += h1*vi.y; acc1[2]  += h1*vi.z; acc1[3]  += h1*vi.w;
            acc1[4]  += h1*vf.x; acc1[5]  += h1*vf.y; acc1[6]  += h1*vf.z; acc1[7]  += h1*vf.w;
            acc1[8]  += h1*vc.x; acc1[9]  += h1*vc.y; acc1[10] += h1*vc.z; acc1[11] += h1*vc.w;
            acc1[12] += h1*vo.x; acc1[13] += h1*vo.y; acc1[14] += h1*vo.z; acc1[15] += h1*vo.w;
        }
        __syncthreads();

        {
            float* row = &sm[tid*33];
            #pragma unroll
            for (int v = 0; v < 16; v++) row[v]    = acc0[v];
            #pragma unroll
            for (int v = 0; v < 16; v++) row[16+v] = acc1[v];
        }
        __syncthreads();

        if (tid < 128) {
            float z0 = 0.f, z1 = 0.f, z2 = 0.f, z3 = 0.f;
            #pragma unroll
            for (int q = 0; q < 16; q++) {
                const float* r = &sm[(q*16 + e_p2*4 + e_jg)*33 + e_b2*16];
                z0 += r[0*4 + e_jj];
                z1 += r[1*4 + e_jj];
                z2 += r[2*4 + e_jj];
                z3 += r[3*4 + e_jj];
            }
            const float* gr = g_G + ((size_t)t * Bdim + e_b) * NG + e_j;
            z0 += gr[0];     // i
            z1 += gr[512];   // f
            z2 += gr[1024];  // g
            z3 += gr[1536];  // o
            float iv = 1.f / (1.f + __expf(-z0));
            float fv = 1.f / (1.f + __expf(-z1));
            float gv = tanhf(z2);
            float ov = 1.f / (1.f + __expf(-z3));
            cstate = fv * cstate + iv * gv;
            float hn = ov * tanhf(cstate);
            g_h[(t+1) & 1][e_idx] = hn;
            out[((size_t)e_b * Tdim + t) * Hdim + e_j] = hn;
        }

        __threadfence();
        __syncthreads();
        if (tid == 0) {
            atomicAdd(&g_bar, 1u);
            unsigned target = (unsigned)gridDim.x * (unsigned)(t + 1);
            unsigned v;
            do {
                asm volatile("ld.acquire.gpu.global.u32 %0, [%1];" : "=r"(v) : "l"(&g_bar));
            } while (v < target);
        }
        __syncthreads();
    }
}

// ---------------------------------------------------------------------------
extern "C" void kernel_launch(void* const* d_in, const int* in_sizes, int n_in,
                              void* d_out, int out_size) {
    const float* X           = (const float*)d_in[0];
    const float* init_states = (const float*)d_in[1];
    const float* Wi = (const float*)d_in[2];
    const float* Ui = (const float*)d_in[3];
    const float* bi = (const float*)d_in[4];
    const float* Wf = (const float*)d_in[5];
    const float* Uf = (const float*)d_in[6];
    const float* bf = (const float*)d_in[7];
    const float* Wc = (const float*)d_in[8];
    const float* Uc = (const float*)d_in[9];
    const float* bc = (const float*)d_in[10];
    const float* Wo = (const float*)d_in[11];
    const float* Uo = (const float*)d_in[12];
    const float* bo = (const float*)d_in[13];
    float* out = (float*)d_out;

    init_kernel<<<(Bdim*Hdim + 255)/256, 256>>>(init_states, bi, bf, bc, bo);

    prep_x_kernel<<<(Tdim*Bdim*DIdim/4 + 255)/256, 256>>>(X);
    prep_w_kernel<<<(DIdim*NG/4 + 255)/256, 256>>>(Wi, Wf, Wc, Wo);

    dim3 gemm_grid((Bdim*Tdim)/128, NG/64);   // (256, 32)
    xw_mma_kernel<<<gemm_grid, 256>>>();

    lstm_kernel<<<128, 256>>>(Ui, Uf, Uc, Uo, init_states, out);
}

// round 5
// speedup vs baseline: 1.9961x; 1.7241x over previous
#include <cuda_runtime.h>
#include <math.h>

#define Bdim 32
#define Tdim 1024
#define DIdim 512
#define Hdim 512
#define NG (4*Hdim)

// Scratch (device globals)
__device__ float    g_G[Tdim*Bdim*NG];       // 268MB: [t][b][gate*512+j] = x@W + bias
__device__ unsigned g_A[Tdim*Bdim*DIdim];    // tf32(X) gathered, row m=t*32+b
__device__ unsigned g_Wt[DIdim*NG];          // tf32(W) fused [k][gate*512+c]
__device__ unsigned g_Ut[Hdim*NG];           // tf32(U) fused, block-interleaved: [k][(j>>2)*16 + g*4 + (j&3)]
__device__ float    g_bias[NG];
__device__ float    g_h[2][Bdim*Hdim];       // fp32 hidden state, double-buffered
__device__ unsigned int g_bar;

__device__ __forceinline__ unsigned f2tf32(float f) {
    unsigned r;
    asm("cvt.rna.tf32.f32 %0, %1;" : "=r"(r) : "f"(f));
    return r;
}

__device__ __forceinline__ void mma_tf32(float* d, const unsigned* a, const unsigned* b) {
    asm volatile(
        "mma.sync.aligned.m16n8k8.row.col.f32.tf32.tf32.f32 "
        "{%0,%1,%2,%3}, {%4,%5,%6,%7}, {%8,%9}, {%0,%1,%2,%3};"
        : "+f"(d[0]), "+f"(d[1]), "+f"(d[2]), "+f"(d[3])
        : "r"(a[0]), "r"(a[1]), "r"(a[2]), "r"(a[3]), "r"(b[0]), "r"(b[1]));
}

// ---------------------------------------------------------------------------
__global__ void init_kernel(const float* __restrict__ init_states,
                            const float* __restrict__ bi, const float* __restrict__ bf,
                            const float* __restrict__ bc, const float* __restrict__ bo)
{
    int i = blockIdx.x * blockDim.x + threadIdx.x;
    if (i < Bdim*Hdim) {
        g_h[0][i] = init_states[i];          // h0 (fp32)
    }
    if (i < NG) {
        int gate = i >> 9, c = i & 511;
        const float* b = (gate==0) ? bi : (gate==1) ? bf : (gate==2) ? bc : bo;
        g_bias[i] = b[c];
    }
    if (i == 0) g_bar = 0u;
}

// ---------------------------------------------------------------------------
__global__ __launch_bounds__(256) void prep_x_kernel(const float* __restrict__ X) {
    int idx = blockIdx.x * blockDim.x + threadIdx.x;
    int m  = idx >> 7;
    int k4 = idx & 127;
    int b = m & 31, t = m >> 5;
    float4 v = *(const float4*)(X + ((size_t)b * Tdim + t) * DIdim + k4*4);
    uint4 o;
    o.x = f2tf32(v.x); o.y = f2tf32(v.y); o.z = f2tf32(v.z); o.w = f2tf32(v.w);
    *(uint4*)(g_A + (size_t)m * DIdim + k4*4) = o;
}

__global__ __launch_bounds__(256) void prep_w_kernel(
    const float* __restrict__ Wi, const float* __restrict__ Wf,
    const float* __restrict__ Wc, const float* __restrict__ Wo)
{
    int idx = blockIdx.x * blockDim.x + threadIdx.x;
    int gate = idx >> 16;
    int rem  = idx & 65535;
    int k  = rem >> 7;
    int c4 = rem & 127;
    const float* W = (gate==0) ? Wi : (gate==1) ? Wf : (gate==2) ? Wc : Wo;
    float4 v = *(const float4*)(W + (size_t)k * Hdim + c4*4);
    uint4 o;
    o.x = f2tf32(v.x); o.y = f2tf32(v.y); o.z = f2tf32(v.z); o.w = f2tf32(v.w);
    *(uint4*)(g_Wt + (size_t)k * NG + gate*512 + c4*4) = o;
}

// U fused + block-interleaved: g_Ut[k][ (j>>2)*16 + gate*4 + (j&3) ]
__global__ __launch_bounds__(256) void prep_u_kernel(
    const float* __restrict__ Ui, const float* __restrict__ Uf,
    const float* __restrict__ Uc, const float* __restrict__ Uo)
{
    int idx = blockIdx.x * blockDim.x + threadIdx.x;
    int gate = idx >> 16;
    int rem  = idx & 65535;
    int k  = rem >> 7;
    int jq = rem & 127;
    const float* U = (gate==0) ? Ui : (gate==1) ? Uf : (gate==2) ? Uc : Uo;
    float4 v = *(const float4*)(U + (size_t)k * Hdim + jq*4);
    uint4 o;
    o.x = f2tf32(v.x); o.y = f2tf32(v.y); o.z = f2tf32(v.z); o.w = f2tf32(v.w);
    *(uint4*)(g_Ut + (size_t)k * NG + jq*16 + gate*4) = o;
}

// ---------------------------------------------------------------------------
// xw GEMM (unchanged, verified): C[32768,2048] = A @ Wt + bias -> g_G
// ---------------------------------------------------------------------------
#define AS_PAD 36
#define BS_PAD 68

__global__ __launch_bounds__(256) void xw_mma_kernel() {
    __shared__ unsigned As[128 * AS_PAD];
    __shared__ unsigned Bs[32 * BS_PAD];

    const int tid = threadIdx.x;
    const int wid = tid >> 5;
    const int lane = tid & 31;
    const int gid = lane >> 2;
    const int tig = lane & 3;

    const int warp_m = (wid & 3) * 32;
    const int warp_n = (wid >> 2) * 32;

    const int mbase = blockIdx.x * 128;
    const int nbase = blockIdx.y * 64;

    float acc[2][4][4];
    #pragma unroll
    for (int mt = 0; mt < 2; mt++)
        #pragma unroll
        for (int nt = 0; nt < 4; nt++)
            #pragma unroll
            for (int r = 0; r < 4; r++) acc[mt][nt][r] = 0.f;

    for (int k0 = 0; k0 < DIdim; k0 += 32) {
        #pragma unroll
        for (int r = 0; r < 4; r++) {
            int i = tid + r * 256;
            int row = i >> 3;
            int k4 = (i & 7) * 4;
            uint4 v = *(const uint4*)(g_A + (size_t)(mbase + row) * DIdim + k0 + k4);
            *(uint4*)&As[row * AS_PAD + k4] = v;
        }
        #pragma unroll
        for (int r = 0; r < 2; r++) {
            int i = tid + r * 256;
            int krow = i >> 4;
            int n4 = (i & 15) * 4;
            uint4 v = *(const uint4*)(g_Wt + (size_t)(k0 + krow) * NG + nbase + n4);
            *(uint4*)&Bs[krow * BS_PAD + n4] = v;
        }
        __syncthreads();

        #pragma unroll
        for (int ks = 0; ks < 4; ks++) {
            const int k8 = ks * 8;
            unsigned af[2][4];
            #pragma unroll
            for (int mt = 0; mt < 2; mt++) {
                int row = warp_m + mt*16 + gid;
                af[mt][0] = As[(row    ) * AS_PAD + k8 + tig    ];
                af[mt][1] = As[(row + 8) * AS_PAD + k8 + tig    ];
                af[mt][2] = As[(row    ) * AS_PAD + k8 + tig + 4];
                af[mt][3] = As[(row + 8) * AS_PAD + k8 + tig + 4];
            }
            unsigned bf2[4][2];
            #pragma unroll
            for (int nt = 0; nt < 4; nt++) {
                int col = warp_n + nt*8 + gid;
                bf2[nt][0] = Bs[(k8 + tig    ) * BS_PAD + col];
                bf2[nt][1] = Bs[(k8 + tig + 4) * BS_PAD + col];
            }
            #pragma unroll
            for (int mt = 0; mt < 2; mt++)
                #pragma unroll
                for (int nt = 0; nt < 4; nt++)
                    mma_tf32(acc[mt][nt], af[mt], bf2[nt]);
        }
        __syncthreads();
    }

    #pragma unroll
    for (int mt = 0; mt < 2; mt++) {
        #pragma unroll
        for (int nt = 0; nt < 4; nt++) {
            int col = nbase + warp_n + nt*8 + 2*tig;
            float b0 = g_bias[col];
            float b1 = g_bias[col + 1];
            int row0 = mbase + warp_m + mt*16 + gid;
            float2 o0 = make_float2(acc[mt][nt][0] + b0, acc[mt][nt][1] + b1);
            float2 o1 = make_float2(acc[mt][nt][2] + b0, acc[mt][nt][3] + b1);
            *(float2*)(g_G + (size_t)row0 * NG + col)       = o0;
            *(float2*)(g_G + (size_t)(row0 + 8) * NG + col) = o1;
        }
    }
}

// ---------------------------------------------------------------------------
// Persistent tensor-core recurrence. 128 CTAs x 256 threads (1/SM).
// CTA: 4 hidden cols (jb = blockIdx.x*4) x 4 gates x 32 batches.
// Warps: w = mt*4 + kh  (mt = w>>2, kh = w&3).
// Warp tile: m16 (mt) x n16 (both ntiles) x k128 (kh).
// h kept fp32; split into tf32 hi/lo at fragment load (two mma chains, one acc).
// U b-fragments (tf32) live in registers for the whole kernel.
// smem (floats): h[32][516] | pbuf[8][290]
// ---------------------------------------------------------------------------
#define SH_H 0
#define SH_P 16512
#define SH_TOTAL (SH_P + 8*290)

__global__ __launch_bounds__(256,1) void lstm_kernel(
    const float* __restrict__ init_states,
    float* __restrict__ out)
{
    extern __shared__ __align__(16) float smf[];

    const int tid  = threadIdx.x;
    const int w    = tid >> 5;
    const int lane = tid & 31;
    const int gid  = lane >> 2;
    const int tig  = lane & 3;
    const int kh   = w & 3;        // k-quarter (128 k each)
    const int mt   = w >> 2;       // m-tile (16 batches each)  [FIXED: was w>>3]
    const int jb   = blockIdx.x * 4;
    const int kbase = kh * 128;

    // --- preload U fragments into registers (once): ub[nt][ks][2] ---
    unsigned ub[2][16][2];
    {
        #pragma unroll
        for (int nt = 0; nt < 2; nt++) {
            const unsigned* Ucol = g_Ut + (size_t)kbase * NG + blockIdx.x*16 + nt*8 + gid;
            #pragma unroll
            for (int ks = 0; ks < 16; ks++) {
                ub[nt][ks][0] = Ucol[(size_t)(ks*8 + tig    ) * NG];
                ub[nt][ks][1] = Ucol[(size_t)(ks*8 + tig + 4) * NG];
            }
        }
    }

    // owner mapping (tid < 128): one (batch, jj) cell each
    const int o_b  = tid >> 2;     // 0..31
    const int o_jj = tid & 3;
    const int o_mt = o_b >> 4;
    const int o_row = o_b & 15;
    float cstate = 0.f;
    if (tid < 128) cstate = init_states[Bdim*Hdim + o_b*Hdim + jb + o_jj];

    for (int t = 0; t < Tdim; t++) {
        // prefetch G (DRAM; consumed after mma+reduce)
        float pg0=0.f, pg1=0.f, pg2=0.f, pg3=0.f;
        if (tid < 128) {
            const float* gr = g_G + ((size_t)t * Bdim + o_b) * NG + jb + o_jj;
            pg0 = __ldcg(gr);
            pg1 = __ldcg(gr + 512);
            pg2 = __ldcg(gr + 1024);
            pg3 = __ldcg(gr + 1536);
        }

        // stage h (fp32) global -> smem: 32 rows x 512 = 4096 float4
        {
            const float4* hsrc = (const float4*)(g_h[t & 1]);
            #pragma unroll
            for (int i = 0; i < 16; i++) {
                int idx = tid + i*256;          // 0..4095
                float4 v = __ldcg(hsrc + idx);
                int bl = idx >> 7;              // 0..31
                int k4 = idx & 127;
                *(float4*)&smf[SH_H + bl*516 + k4*4] = v;
            }
        }
        __syncthreads();

        // mma: warp tile m16 x n16, K=128 (16 k8-steps), hi+lo chains
        float acc[2][4];
        #pragma unroll
        for (int nt = 0; nt < 2; nt++)
            #pragma unroll
            for (int r = 0; r < 4; r++) acc[nt][r] = 0.f;
        {
            const int row = mt*16 + gid;
            const float* hs = &smf[SH_H + row*516 + kbase + tig];
            #pragma unroll
            for (int ks = 0; ks < 16; ks++) {
                float h0 = hs[ks*8];
                float h1 = hs[ks*8 + 8*516];
                float h2 = hs[ks*8 + 4];
                float h3 = hs[ks*8 + 8*516 + 4];
                unsigned ahi[4], alo[4];
                ahi[0] = f2tf32(h0); alo[0] = f2tf32(h0 - __uint_as_float(ahi[0]));
                ahi[1] = f2tf32(h1); alo[1] = f2tf32(h1 - __uint_as_float(ahi[1]));
                ahi[2] = f2tf32(h2); alo[2] = f2tf32(h2 - __uint_as_float(ahi[2]));
                ahi[3] = f2tf32(h3); alo[3] = f2tf32(h3 - __uint_as_float(ahi[3]));
                mma_tf32(acc[0], ahi, ub[0][ks]);
                mma_tf32(acc[1], ahi, ub[1][ks]);
                mma_tf32(acc[0], alo, ub[0][ks]);
                mma_tf32(acc[1], alo, ub[1][ks]);
            }
        }

        // all warps stash partials: pbuf[w][row16][n16] (row stride 18, blk 290)
        {
            float* pb = &smf[SH_P + w*290];
            #pragma unroll
            for (int nt = 0; nt < 2; nt++) {
                *(float2*)&pb[ gid     *18 + nt*8 + 2*tig] = make_float2(acc[nt][0], acc[nt][1]);
                *(float2*)&pb[(gid + 8)*18 + nt*8 + 2*tig] = make_float2(acc[nt][2], acc[nt][3]);
            }
        }
        __syncthreads();

        // owners: 4-way k-reduce + G + LSTM cell
        if (tid < 128) {
            const float* pb = &smf[SH_P + (o_mt*4)*290 + o_row*18 + o_jj];
            float z0 = pg0, z1 = pg1, z2 = pg2, z3 = pg3;
            #pragma unroll
            for (int q = 0; q < 4; q++) {
                const float* r = pb + q*290;
                z0 += r[0];    // gate i  (n = 0*4 + jj)
                z1 += r[4];    // gate f
                z2 += r[8];    // gate g
                z3 += r[12];   // gate o
            }
            float iv = 1.f / (1.f + __expf(-z0));
            float fv = 1.f / (1.f + __expf(-z1));
            float gv = tanhf(z2);
            float ov = 1.f / (1.f + __expf(-z3));
            cstate = fv * cstate + iv * gv;
            float hn = ov * tanhf(cstate);
            out[((size_t)o_b * Tdim + t) * Hdim + jb + o_jj] = hn;
            g_h[(t+1) & 1][o_b*Hdim + jb + o_jj] = hn;
        }

        // grid barrier
        __threadfence();
        __syncthreads();
        if (tid == 0) {
            atomicAdd(&g_bar, 1u);
            unsigned target = (unsigned)gridDim.x * (unsigned)(t + 1);
            unsigned v;
            do {
                asm volatile("ld.acquire.gpu.global.u32 %0, [%1];" : "=r"(v) : "l"(&g_bar));
            } while (v < target);
        }
        __syncthreads();
    }
}

// ---------------------------------------------------------------------------
extern "C" void kernel_launch(void* const* d_in, const int* in_sizes, int n_in,
                              void* d_out, int out_size) {
    const float* X           = (const float*)d_in[0];
    const float* init_states = (const float*)d_in[1];
    const float* Wi = (const float*)d_in[2];
    const float* Ui = (const float*)d_in[3];
    const float* bi = (const float*)d_in[4];
    const float* Wf = (const float*)d_in[5];
    const float* Uf = (const float*)d_in[6];
    const float* bf = (const float*)d_in[7];
    const float* Wc = (const float*)d_in[8];
    const float* Uc = (const float*)d_in[9];
    const float* bc = (const float*)d_in[10];
    const float* Wo = (const float*)d_in[11];
    const float* Uo = (const float*)d_in[12];
    const float* bo = (const float*)d_in[13];
    float* out = (float*)d_out;

    cudaFuncSetAttribute(lstm_kernel, cudaFuncAttributeMaxDynamicSharedMemorySize,
                         SH_TOTAL * 4);

    init_kernel<<<(Bdim*Hdim + 255)/256, 256>>>(init_states, bi, bf, bc, bo);

    prep_x_kernel<<<(Tdim*Bdim*DIdim/4 + 255)/256, 256>>>(X);
    prep_w_kernel<<<(DIdim*NG/4 + 255)/256, 256>>>(Wi, Wf, Wc, Wo);
    prep_u_kernel<<<(Hdim*NG/4 + 255)/256, 256>>>(Ui, Uf, Uc, Uo);

    dim3 gemm_grid((Bdim*Tdim)/128, NG/64);
    xw_mma_kernel<<<gemm_grid, 256>>>();

    lstm_kernel<<<128, 256, SH_TOTAL*4>>>(init_states, out);
}

// round 6
// speedup vs baseline: 2.1242x; 1.0642x over previous
#include <cuda_runtime.h>
#include <math.h>

#define Bdim 32
#define Tdim 1024
#define DIdim 512
#define Hdim 512
#define NG (4*Hdim)

#define HROW 516                       // padded h row (floats)
#define H_SLICE_BYTES 16512u           // 8 rows * 516 * 4
#define H_BYTES 66048u                 // 32 rows * 516 * 4

// Scratch (device globals)
__device__ float    g_G[Tdim*Bdim*NG];        // [t][b][gate*512+j] = x@W + bias
__device__ unsigned g_A[Tdim*Bdim*DIdim];     // tf32(X) gathered, row m=t*32+b
__device__ unsigned g_Wt[DIdim*NG];           // tf32(W) fused [k][gate*512+c]
__device__ unsigned g_Ut[Hdim*NG];            // tf32(U) fused block-interleaved
__device__ float    g_bias[NG];
__device__ __align__(16) float g_h[2][32*HROW];  // fp32 h, PADDED layout, double-buffered
__device__ unsigned int g_bar;

__device__ __forceinline__ unsigned f2tf32(float f) {
    unsigned r;
    asm("cvt.rna.tf32.f32 %0, %1;" : "=r"(r) : "f"(f));
    return r;
}

__device__ __forceinline__ void mma_tf32(float* d, const unsigned* a, const unsigned* b) {
    asm volatile(
        "mma.sync.aligned.m16n8k8.row.col.f32.tf32.tf32.f32 "
        "{%0,%1,%2,%3}, {%4,%5,%6,%7}, {%8,%9}, {%0,%1,%2,%3};"
        : "+f"(d[0]), "+f"(d[1]), "+f"(d[2]), "+f"(d[3])
        : "r"(a[0]), "r"(a[1]), "r"(a[2]), "r"(a[3]), "r"(b[0]), "r"(b[1]));
}

// ---------------------------------------------------------------------------
__global__ void init_kernel(const float* __restrict__ init_states,
                            const float* __restrict__ bi, const float* __restrict__ bf,
                            const float* __restrict__ bc, const float* __restrict__ bo)
{
    int i = blockIdx.x * blockDim.x + threadIdx.x;
    if (i < Bdim*Hdim) {
        int b = i >> 9, j = i & 511;
        g_h[0][b*HROW + j] = init_states[i];    // h0 into padded layout
    }
    if (i < NG) {
        int gate = i >> 9, c = i & 511;
        const float* b = (gate==0) ? bi : (gate==1) ? bf : (gate==2) ? bc : bo;
        g_bias[i] = b[c];
    }
    if (i == 0) g_bar = 0u;
}

// ---------------------------------------------------------------------------
__global__ __launch_bounds__(256) void prep_x_kernel(const float* __restrict__ X) {
    int idx = blockIdx.x * blockDim.x + threadIdx.x;
    int m  = idx >> 7;
    int k4 = idx & 127;
    int b = m & 31, t = m >> 5;
    float4 v = *(const float4*)(X + ((size_t)b * Tdim + t) * DIdim + k4*4);
    uint4 o;
    o.x = f2tf32(v.x); o.y = f2tf32(v.y); o.z = f2tf32(v.z); o.w = f2tf32(v.w);
    *(uint4*)(g_A + (size_t)m * DIdim + k4*4) = o;
}

__global__ __launch_bounds__(256) void prep_w_kernel(
    const float* __restrict__ Wi, const float* __restrict__ Wf,
    const float* __restrict__ Wc, const float* __restrict__ Wo)
{
    int idx = blockIdx.x * blockDim.x + threadIdx.x;
    int gate = idx >> 16;
    int rem  = idx & 65535;
    int k  = rem >> 7;
    int c4 = rem & 127;
    const float* W = (gate==0) ? Wi : (gate==1) ? Wf : (gate==2) ? Wc : Wo;
    float4 v = *(const float4*)(W + (size_t)k * Hdim + c4*4);
    uint4 o;
    o.x = f2tf32(v.x); o.y = f2tf32(v.y); o.z = f2tf32(v.z); o.w = f2tf32(v.w);
    *(uint4*)(g_Wt + (size_t)k * NG + gate*512 + c4*4) = o;
}

// U fused + block-interleaved: g_Ut[k][ (j>>2)*16 + gate*4 + (j&3) ]
__global__ __launch_bounds__(256) void prep_u_kernel(
    const float* __restrict__ Ui, const float* __restrict__ Uf,
    const float* __restrict__ Uc, const float* __restrict__ Uo)
{
    int idx = blockIdx.x * blockDim.x + threadIdx.x;
    int gate = idx >> 16;
    int rem  = idx & 65535;
    int k  = rem >> 7;
    int jq = rem & 127;
    const float* U = (gate==0) ? Ui : (gate==1) ? Uf : (gate==2) ? Uc : Uo;
    float4 v = *(const float4*)(U + (size_t)k * Hdim + jq*4);
    uint4 o;
    o.x = f2tf32(v.x); o.y = f2tf32(v.y); o.z = f2tf32(v.z); o.w = f2tf32(v.w);
    *(uint4*)(g_Ut + (size_t)k * NG + jq*16 + gate*4) = o;
}

// ---------------------------------------------------------------------------
// xw GEMM (unchanged, verified): C[32768,2048] = A @ Wt + bias -> g_G
// ---------------------------------------------------------------------------
#define AS_PAD 36
#define BS_PAD 68

__global__ __launch_bounds__(256) void xw_mma_kernel() {
    __shared__ unsigned As[128 * AS_PAD];
    __shared__ unsigned Bs[32 * BS_PAD];

    const int tid = threadIdx.x;
    const int wid = tid >> 5;
    const int lane = tid & 31;
    const int gid = lane >> 2;
    const int tig = lane & 3;

    const int warp_m = (wid & 3) * 32;
    const int warp_n = (wid >> 2) * 32;

    const int mbase = blockIdx.x * 128;
    const int nbase = blockIdx.y * 64;

    float acc[2][4][4];
    #pragma unroll
    for (int mt = 0; mt < 2; mt++)
        #pragma unroll
        for (int nt = 0; nt < 4; nt++)
            #pragma unroll
            for (int r = 0; r < 4; r++) acc[mt][nt][r] = 0.f;

    for (int k0 = 0; k0 < DIdim; k0 += 32) {
        #pragma unroll
        for (int r = 0; r < 4; r++) {
            int i = tid + r * 256;
            int row = i >> 3;
            int k4 = (i & 7) * 4;
            uint4 v = *(const uint4*)(g_A + (size_t)(mbase + row) * DIdim + k0 + k4);
            *(uint4*)&As[row * AS_PAD + k4] = v;
        }
        #pragma unroll
        for (int r = 0; r < 2; r++) {
            int i = tid + r * 256;
            int krow = i >> 4;
            int n4 = (i & 15) * 4;
            uint4 v = *(const uint4*)(g_Wt + (size_t)(k0 + krow) * NG + nbase + n4);
            *(uint4*)&Bs[krow * BS_PAD + n4] = v;
        }
        __syncthreads();

        #pragma unroll
        for (int ks = 0; ks < 4; ks++) {
            const int k8 = ks * 8;
            unsigned af[2][4];
            #pragma unroll
            for (int mt = 0; mt < 2; mt++) {
                int row = warp_m + mt*16 + gid;
                af[mt][0] = As[(row    ) * AS_PAD + k8 + tig    ];
                af[mt][1] = As[(row + 8) * AS_PAD + k8 + tig    ];
                af[mt][2] = As[(row    ) * AS_PAD + k8 + tig + 4];
                af[mt][3] = As[(row + 8) * AS_PAD + k8 + tig + 4];
            }
            unsigned bf2[4][2];
            #pragma unroll
            for (int nt = 0; nt < 4; nt++) {
                int col = warp_n + nt*8 + gid;
                bf2[nt][0] = Bs[(k8 + tig    ) * BS_PAD + col];
                bf2[nt][1] = Bs[(k8 + tig + 4) * BS_PAD + col];
            }
            #pragma unroll
            for (int mt = 0; mt < 2; mt++)
                #pragma unroll
                for (int nt = 0; nt < 4; nt++)
                    mma_tf32(acc[mt][nt], af[mt], bf2[nt]);
        }
        __syncthreads();
    }

    #pragma unroll
    for (int mt = 0; mt < 2; mt++) {
        #pragma unroll
        for (int nt = 0; nt < 4; nt++) {
            int col = nbase + warp_n + nt*8 + 2*tig;
            float b0 = g_bias[col];
            float b1 = g_bias[col + 1];
            int row0 = mbase + warp_m + mt*16 + gid;
            float2 o0 = make_float2(acc[mt][nt][0] + b0, acc[mt][nt][1] + b1);
            float2 o1 = make_float2(acc[mt][nt][2] + b0, acc[mt][nt][3] + b1);
            *(float2*)(g_G + (size_t)row0 * NG + col)       = o0;
            *(float2*)(g_G + (size_t)(row0 + 8) * NG + col) = o1;
        }
    }
}

// ---------------------------------------------------------------------------
// Persistent tensor-core recurrence. 128 CTAs x 256 threads, clusters of 4.
// h all-gather via cooperative-sliced TMA bulk MULTICAST (each CTA loads its
// rank's 8-batch slice, multicast to all 4 -> every CTA gets full 64KB;
// L2 traffic /4). h stored padded (stride 516) so TMA lands conflict-free.
// Warps: w = mt*4 + kh. Warp tile m16 x n16 x k128. hi/lo tf32 split of fp32 h
// with SEPARATE accumulator chains (depth 16, merged at stash).
// ---------------------------------------------------------------------------
#define SH_H 0
#define SH_P 16512                       // floats (== 32*516)
#define SH_TOTAL (SH_P + 8*290)          // floats
#define SMEM_BYTES (SH_TOTAL*4 + 16)     // + mbarrier

__global__ __launch_bounds__(256,1) __cluster_dims__(4,1,1)
void lstm_kernel(const float* __restrict__ init_states,
                 float* __restrict__ out)
{
    extern __shared__ __align__(16) float smf[];

    const int tid  = threadIdx.x;
    const int w    = tid >> 5;
    const int lane = tid & 31;
    const int gid  = lane >> 2;
    const int tig  = lane & 3;
    const int kh   = w & 3;        // k-quarter (128 k each)
    const int mt   = w >> 2;       // m-tile (16 batches each)
    const int jb   = blockIdx.x * 4;
    const int kbase = kh * 128;

    unsigned smem_u32;
    asm("{ .reg .u64 t0; cvta.to.shared.u64 t0, %1; cvt.u32.u64 %0, t0; }"
        : "=r"(smem_u32) : "l"(smf));
    const unsigned mbar = smem_u32 + SH_TOTAL*4;

    unsigned rank;
    asm("mov.u32 %0, %%cluster_ctarank;" : "=r"(rank));

    // --- preload U fragments into registers (once): ub[nt][ks][2] ---
    unsigned ub[2][16][2];
    {
        #pragma unroll
        for (int nt = 0; nt < 2; nt++) {
            const unsigned* Ucol = g_Ut + (size_t)kbase * NG + blockIdx.x*16 + nt*8 + gid;
            #pragma unroll
            for (int ks = 0; ks < 16; ks++) {
                ub[nt][ks][0] = Ucol[(size_t)(ks*8 + tig    ) * NG];
                ub[nt][ks][1] = Ucol[(size_t)(ks*8 + tig + 4) * NG];
            }
        }
    }

    // owner mapping (tid < 128): one (batch, jj) cell each
    const int o_b  = tid >> 2;     // 0..31
    const int o_jj = tid & 3;
    const int o_mt = o_b >> 4;
    const int o_row = o_b & 15;
    float cstate = 0.f;
    if (tid < 128) cstate = init_states[Bdim*Hdim + o_b*Hdim + jb + o_jj];

    // mbarrier init + cluster sync (peers' multicast needs my mbar live)
    if (tid == 0) {
        asm volatile("mbarrier.init.shared.b64 [%0], 1;" :: "r"(mbar) : "memory");
    }
    __syncthreads();
    asm volatile("barrier.cluster.arrive.aligned;" ::: "memory");
    asm volatile("barrier.cluster.wait.aligned;" ::: "memory");

    float hn = 0.f;   // carried for deferred out-store

    for (int t = 0; t < Tdim; t++) {
        // prefetch G (DRAM; consumed after mma+reduce)
        float pg0=0.f, pg1=0.f, pg2=0.f, pg3=0.f;
        if (tid < 128) {
            const float* gr = g_G + ((size_t)t * Bdim + o_b) * NG + jb + o_jj;
            pg0 = __ldcg(gr);
            pg1 = __ldcg(gr + 512);
            pg2 = __ldcg(gr + 1024);
            pg3 = __ldcg(gr + 1536);
        }

        // ---- cooperative-sliced TMA multicast of h ----
        if (tid == 0) {
            asm volatile("mbarrier.arrive.expect_tx.shared.b64 _, [%0], %1;"
                         :: "r"(mbar), "r"(H_BYTES) : "memory");
            const char* src = (const char*)(g_h[t & 1]) + rank * H_SLICE_BYTES;
            unsigned dst = smem_u32 + rank * H_SLICE_BYTES;
            asm volatile(
                "cp.async.bulk.shared::cluster.global.mbarrier::complete_tx::bytes.multicast::cluster "
                "[%0], [%1], %2, [%3], %4;"
                :: "r"(dst), "l"(src), "r"(H_SLICE_BYTES), "r"(mbar),
                   "h"((unsigned short)0xF) : "memory");
        }
        // wait for full 64KB (4 slices, incl. peers')
        {
            unsigned parity = t & 1;
            asm volatile(
                "{\n\t.reg .pred P;\n"
                "W%=:\n\t"
                "mbarrier.try_wait.parity.acquire.cta.shared::cta.b64 P, [%0], %1, 0x989680;\n\t"
                "@P bra D%=;\n\t"
                "bra W%=;\n"
                "D%=:\n\t}"
                :: "r"(mbar), "r"(parity) : "memory");
        }

        // mma: warp tile m16 x n16, K=128; hi/lo SEPARATE chains (depth 16)
        float acch[2][4], accl[2][4];
        #pragma unroll
        for (int nt = 0; nt < 2; nt++)
            #pragma unroll
            for (int r = 0; r < 4; r++) { acch[nt][r] = 0.f; accl[nt][r] = 0.f; }
        {
            const int row = mt*16 + gid;
            const float* hs = &smf[SH_H + row*HROW + kbase + tig];
            #pragma unroll
            for (int ks = 0; ks < 16; ks++) {
                float h0 = hs[ks*8];
                float h1 = hs[ks*8 + 8*HROW];
                float h2 = hs[ks*8 + 4];
                float h3 = hs[ks*8 + 8*HROW + 4];
                unsigned ahi[4], alo[4];
                ahi[0] = f2tf32(h0); alo[0] = f2tf32(h0 - __uint_as_float(ahi[0]));
                ahi[1] = f2tf32(h1); alo[1] = f2tf32(h1 - __uint_as_float(ahi[1]));
                ahi[2] = f2tf32(h2); alo[2] = f2tf32(h2 - __uint_as_float(ahi[2]));
                ahi[3] = f2tf32(h3); alo[3] = f2tf32(h3 - __uint_as_float(ahi[3]));
                mma_tf32(acch[0], ahi, ub[0][ks]);
                mma_tf32(acch[1], ahi, ub[1][ks]);
                mma_tf32(accl[0], alo, ub[0][ks]);
                mma_tf32(accl[1], alo, ub[1][ks]);
            }
        }
        __syncthreads();   // all lanes done reading smem h (TMA next step rewrites)

        // stash merged partials: pbuf[w][row16][n16] (row stride 18, blk 290)
        {
            float* pb = &smf[SH_P + w*290];
            #pragma unroll
            for (int nt = 0; nt < 2; nt++) {
                *(float2*)&pb[ gid     *18 + nt*8 + 2*tig] =
                    make_float2(acch[nt][0] + accl[nt][0], acch[nt][1] + accl[nt][1]);
                *(float2*)&pb[(gid + 8)*18 + nt*8 + 2*tig] =
                    make_float2(acch[nt][2] + accl[nt][2], acch[nt][3] + accl[nt][3]);
            }
        }
        __syncthreads();

        // owners: 4-way k-reduce + G + LSTM cell; write h (padded layout)
        if (tid < 128) {
            const float* pb = &smf[SH_P + (o_mt*4)*290 + o_row*18 + o_jj];
            float z0 = pg0, z1 = pg1, z2 = pg2, z3 = pg3;
            #pragma unroll
            for (int q = 0; q < 4; q++) {
                const float* r = pb + q*290;
                z0 += r[0];    // i
                z1 += r[4];    // f
                z2 += r[8];    // g
                z3 += r[12];   // o
            }
            float iv = 1.f / (1.f + __expf(-z0));
            float fv = 1.f / (1.f + __expf(-z1));
            float gv = tanhf(z2);
            float ov = 1.f / (1.f + __expf(-z3));
            cstate = fv * cstate + iv * gv;
            hn = ov * tanhf(cstate);
            g_h[(t+1) & 1][o_b*HROW + jb + o_jj] = hn;
            __threadfence();   // writers only
        }
        __syncthreads();

        // grid barrier
        if (tid == 0) {
            atomicAdd(&g_bar, 1u);
            unsigned target = (unsigned)gridDim.x * (unsigned)(t + 1);
            unsigned v;
            do {
                asm volatile("ld.acquire.gpu.global.u32 %0, [%1];" : "=r"(v) : "l"(&g_bar));
            } while (v < target);
        }
        __syncthreads();

        // deferred out store (off the fence/barrier critical path)
        if (tid < 128) {
            out[((size_t)o_b * Tdim + t) * Hdim + jb + o_jj] = hn;
        }
    }

    // all in-flight multicast accounted by mbar waits; sync cluster before exit
    asm volatile("barrier.cluster.arrive.aligned;" ::: "memory");
    asm volatile("barrier.cluster.wait.aligned;" ::: "memory");
}

// ---------------------------------------------------------------------------
extern "C" void kernel_launch(void* const* d_in, const int* in_sizes, int n_in,
                              void* d_out, int out_size) {
    const float* X           = (const float*)d_in[0];
    const float* init_states = (const float*)d_in[1];
    const float* Wi = (const float*)d_in[2];
    const float* Ui = (const float*)d_in[3];
    const float* bi = (const float*)d_in[4];
    const float* Wf = (const float*)d_in[5];
    const float* Uf = (const float*)d_in[6];
    const float* bf = (const float*)d_in[7];
    const float* Wc = (const float*)d_in[8];
    const float* Uc = (const float*)d_in[9];
    const float* bc = (const float*)d_in[10];
    const float* Wo = (const float*)d_in[11];
    const float* Uo = (const float*)d_in[12];
    const float* bo = (const float*)d_in[13];
    float* out = (float*)d_out;

    cudaFuncSetAttribute(lstm_kernel, cudaFuncAttributeMaxDynamicSharedMemorySize,
                         SMEM_BYTES);

    init_kernel<<<(Bdim*Hdim + 255)/256, 256>>>(init_states, bi, bf, bc, bo);

    prep_x_kernel<<<(Tdim*Bdim*DIdim/4 + 255)/256, 256>>>(X);
    prep_w_kernel<<<(DIdim*NG/4 + 255)/256, 256>>>(Wi, Wf, Wc, Wo);
    prep_u_kernel<<<(Hdim*NG/4 + 255)/256, 256>>>(Ui, Uf, Uc, Uo);

    dim3 gemm_grid((Bdim*Tdim)/128, NG/64);
    xw_mma_kernel<<<gemm_grid, 256>>>();

    lstm_kernel<<<128, 256, SMEM_BYTES>>>(init_states, out);
}